// round 4
// baseline (speedup 1.0000x reference)
#include <cuda_runtime.h>
#include <cuda_bf16.h>
#include <cstdint>

#define Bv   128
#define Hv   256
#define Tv   2048
#define Vv   32000
#define NTILES 250            // Vv / 128
#define NCH   4               // attention T-chunks

#define LOGP_OFF  0
#define HNEW_OFF  (Bv*Vv)                 // 4,096,000
#define ATTN_OFF  (HNEW_OFF + Bv*Hv)      // 4,128,768
#define CTX_OFF   (ATTN_OFF + Bv*Tv)      // 4,390,912

#define NEG_HUGE  (-3.402823466e38f)

// ---------------- scratch ----------------
__device__ __align__(16) float g_x[Bv * Hv];
__device__ __align__(16) float g_gx[Bv * 3 * Hv];
__device__ __align__(16) float g_gh[Bv * 3 * Hv];
__device__ __align__(16) float g_ht[Hv * Bv];     // h_new transposed [k][b]
__device__ __align__(16) float g_pmax[NTILES * Bv];
__device__ __align__(16) float g_psum[NTILES * Bv];
__device__ __align__(16) float g_am[NCH * Bv];
__device__ __align__(16) float g_al[NCH * Bv];
__device__ __align__(16) float g_actx[NCH * Bv * Hv];

// ---------------- helpers ----------------
__device__ __forceinline__ uint32_t to_tf32(float x) {
    uint32_t r;
    asm("cvt.rna.tf32.f32 %0, %1;" : "=r"(r) : "f"(x));
    return r;
}
__device__ __forceinline__ void mma_tf32(float* c, uint32_t a0, uint32_t a1,
                                         uint32_t a2, uint32_t a3,
                                         uint32_t b0, uint32_t b1) {
    asm("mma.sync.aligned.m16n8k8.row.col.f32.tf32.tf32.f32 "
        "{%0,%1,%2,%3},{%4,%5,%6,%7},{%8,%9},{%0,%1,%2,%3};"
        : "+f"(c[0]), "+f"(c[1]), "+f"(c[2]), "+f"(c[3])
        : "r"(a0), "r"(a1), "r"(a2), "r"(a3), "r"(b0), "r"(b1));
}
__device__ __forceinline__ float tanh_fast(float x) {
    float r;
    asm("tanh.approx.f32 %0, %1;" : "=f"(r) : "f"(x));
    return r;
}
__device__ __forceinline__ float sigmoid_fast(float x) {
    return 0.5f * tanh_fast(0.5f * x) + 0.5f;
}

// ---------------- K1a: attention partial pass (T-chunked) ----------------
// grid (NCH, Bv); each block handles 512 t's for one batch.
__global__ void __launch_bounds__(512) k_attn_part(const float* __restrict__ enc,
                                                   const float* __restrict__ attn_W,
                                                   const float* __restrict__ hidden,
                                                   const float* __restrict__ attn_b,
                                                   float* __restrict__ out) {
    int c = blockIdx.x, b = blockIdx.y;
    int tid = threadIdx.x, w = tid >> 5, lane = tid & 31;
    __shared__ float s_m[16], s_l[16];
    __shared__ __align__(16) float s_ctx[16 * 256];
    __shared__ float s_shred[8];

    // hidden . W_h + attn_b (scalar, redundantly per chunk)
    float hv = 0.f;
    if (tid < 256) hv = hidden[b * Hv + tid] * attn_W[tid];
#pragma unroll
    for (int o = 16; o; o >>= 1) hv += __shfl_xor_sync(0xffffffffu, hv, o);
    if (lane == 0 && w < 8) s_shred[w] = hv;
    __syncthreads();
    float sh = attn_b[0];
#pragma unroll
    for (int i = 0; i < 8; i++) sh += s_shred[i];

    int h0 = lane * 8;
    float4 we0 = *(const float4*)(attn_W + Hv + h0);
    float4 we1 = *(const float4*)(attn_W + Hv + h0 + 4);

    float m0 = NEG_HUGE, l0 = 0.f, m1 = NEG_HUGE, l1 = 0.f;
    float c0[8], c1[8];
#pragma unroll
    for (int j = 0; j < 8; j++) { c0[j] = 0.f; c1[j] = 0.f; }

    const float* base = enc + (size_t)b * Hv + h0;
    const size_t STR = (size_t)Bv * Hv;
    float* rawsc = out + ATTN_OFF + (size_t)b * Tv;

    int tbeg = c * 512 + w;
    int tend = (c + 1) * 512;

    float4 A0, A1, B0, B1;
    {
        const float4* p0 = (const float4*)(base + (size_t)tbeg * STR);
        const float4* p1 = (const float4*)(base + (size_t)(tbeg + 16) * STR);
        A0 = p0[0]; A1 = p0[1]; B0 = p1[0]; B1 = p1[1];
    }

    for (int t0 = tbeg; t0 < tend; t0 += 32) {
        float4 a0 = A0, a1 = A1, b0 = B0, b1 = B1;
        int tn = t0 + 32;
        if (tn < tend) {
            const float4* p0 = (const float4*)(base + (size_t)tn * STR);
            const float4* p1 = (const float4*)(base + (size_t)(tn + 16) * STR);
            A0 = p0[0]; A1 = p0[1]; B0 = p1[0]; B1 = p1[1];
        }

        float ea[8] = {a0.x, a0.y, a0.z, a0.w, a1.x, a1.y, a1.z, a1.w};
        float eb[8] = {b0.x, b0.y, b0.z, b0.w, b1.x, b1.y, b1.z, b1.w};
        float wv[8] = {we0.x, we0.y, we0.z, we0.w, we1.x, we1.y, we1.z, we1.w};

        float s0 = 0.f, s1 = 0.f;
#pragma unroll
        for (int j = 0; j < 8; j++) { s0 += ea[j] * wv[j]; s1 += eb[j] * wv[j]; }
#pragma unroll
        for (int o = 16; o; o >>= 1) {
            s0 += __shfl_xor_sync(0xffffffffu, s0, o);
            s1 += __shfl_xor_sync(0xffffffffu, s1, o);
        }
        s0 += sh; s1 += sh;
        if (lane == 0) { rawsc[t0] = s0; rawsc[t0 + 16] = s1; }

        {
            float mn = fmaxf(m0, s0);
            float cc = __expf(m0 - mn), p = __expf(s0 - mn);
            l0 = l0 * cc + p;
#pragma unroll
            for (int j = 0; j < 8; j++) c0[j] = c0[j] * cc + p * ea[j];
            m0 = mn;
        }
        {
            float mn = fmaxf(m1, s1);
            float cc = __expf(m1 - mn), p = __expf(s1 - mn);
            l1 = l1 * cc + p;
#pragma unroll
            for (int j = 0; j < 8; j++) c1[j] = c1[j] * cc + p * eb[j];
            m1 = mn;
        }
    }

    float Mw = fmaxf(m0, m1);
    float e0 = __expf(m0 - Mw), e1 = __expf(m1 - Mw);
    float Lw = l0 * e0 + l1 * e1;
    s_m[w] = Mw; s_l[w] = Lw;
#pragma unroll
    for (int j = 0; j < 8; j++) s_ctx[w * 256 + h0 + j] = c0[j] * e0 + c1[j] * e1;
    __syncthreads();

    float Mg = NEG_HUGE;
#pragma unroll
    for (int i = 0; i < 16; i++) Mg = fmaxf(Mg, s_m[i]);
    float Lg = 0.f;
#pragma unroll
    for (int i = 0; i < 16; i++) Lg += __expf(s_m[i] - Mg) * s_l[i];

    if (tid == 0) { g_am[c * Bv + b] = Mg; g_al[c * Bv + b] = Lg; }
    if (tid < 256) {
        float acc = 0.f;
#pragma unroll
        for (int i = 0; i < 16; i++) acc += __expf(s_m[i] - Mg) * s_ctx[i * 256 + tid];
        g_actx[(c * Bv + b) * Hv + tid] = acc;
    }
}

// ---------------- K1b: attention finalize ----------------
__global__ void __launch_bounds__(512) k_attn_fin(float* __restrict__ out) {
    int b = blockIdx.x, tid = threadIdx.x;
    __shared__ float fm[NCH], fl[NCH];
    if (tid < NCH) { fm[tid] = g_am[tid * Bv + b]; fl[tid] = g_al[tid * Bv + b]; }
    __syncthreads();
    float Mg = NEG_HUGE;
#pragma unroll
    for (int i = 0; i < NCH; i++) Mg = fmaxf(Mg, fm[i]);
    float Lg = 0.f;
#pragma unroll
    for (int i = 0; i < NCH; i++) Lg += __expf(fm[i] - Mg) * fl[i];
    float invL = 1.f / Lg;

    if (tid < 256) {
        float acc = 0.f;
#pragma unroll
        for (int i = 0; i < NCH; i++)
            acc += __expf(fm[i] - Mg) * g_actx[(i * Bv + b) * Hv + tid];
        out[CTX_OFF + b * Hv + tid] = acc * invL;
    }
    float* rawsc = out + ATTN_OFF + (size_t)b * Tv;
#pragma unroll
    for (int i = 0; i < Tv / 512; i++) {
        int t = i * 512 + tid;
        rawsc[t] = __expf(rawsc[t] - Mg) * invL;
    }
}

// ---------------- K2a: comb linear ----------------
__global__ void __launch_bounds__(256) k_comb(const int* __restrict__ tokens,
                                              const float* __restrict__ emb_table,
                                              const float* __restrict__ comb_W,
                                              const float* __restrict__ comb_b,
                                              const float* __restrict__ out) {
    __shared__ __align__(16) float xs[16][512];
    int tid = threadIdx.x, w = tid >> 5, lane = tid & 31;
    int b0 = blockIdx.y * 16;
    const float* ctx = out + CTX_OFF;

    for (int idx = tid; idx < 16 * 512; idx += 256) {
        int bb = idx >> 9, k = idx & 511;
        int gb = b0 + bb;
        float v;
        if (k < 256) {
            int tok = tokens[gb];
            v = emb_table[(size_t)tok * Hv + k];
        } else {
            v = ctx[gb * Hv + (k - 256)];
        }
        xs[bb][k] = v;
    }
    __syncthreads();

    int n = blockIdx.x * 8 + w;
    const float* wr = comb_W + (size_t)n * 512 + lane * 4;
    float4 w0 = *(const float4*)(wr);
    float4 w1 = *(const float4*)(wr + 128);
    float4 w2 = *(const float4*)(wr + 256);
    float4 w3 = *(const float4*)(wr + 384);
    float bvl = comb_b[n];

#pragma unroll 4
    for (int bb = 0; bb < 16; bb++) {
        const float* xr = &xs[bb][lane * 4];
        float4 x0 = *(const float4*)(xr);
        float4 x1 = *(const float4*)(xr + 128);
        float4 x2 = *(const float4*)(xr + 256);
        float4 x3 = *(const float4*)(xr + 384);
        float p = w0.x * x0.x + w0.y * x0.y + w0.z * x0.z + w0.w * x0.w
                + w1.x * x1.x + w1.y * x1.y + w1.z * x1.z + w1.w * x1.w
                + w2.x * x2.x + w2.y * x2.y + w2.z * x2.z + w2.w * x2.w
                + w3.x * x3.x + w3.y * x3.y + w3.z * x3.z + w3.w * x3.w;
#pragma unroll
        for (int o = 16; o; o >>= 1) p += __shfl_xor_sync(0xffffffffu, p, o);
        if (lane == 0) g_x[(b0 + bb) * Hv + n] = fmaxf(p + bvl, 0.f);
    }
}

// ---------------- K2b: gx and gh ----------------
__global__ void __launch_bounds__(256) k_gxgh(const float* __restrict__ hidden,
                                              const float* __restrict__ Wih,
                                              const float* __restrict__ Whh,
                                              const float* __restrict__ bih,
                                              const float* __restrict__ bhh) {
    __shared__ __align__(16) float xs[32][256];
    int tid = threadIdx.x, w = tid >> 5, lane = tid & 31;
    int b0 = blockIdx.y * 32;
    int z = blockIdx.z;
    const float* X = z ? hidden : g_x;
    const float* W = z ? Whh : Wih;
    const float* bias = z ? bhh : bih;
    float* Y = z ? g_gh : g_gx;

    for (int idx = tid; idx < 32 * 256; idx += 256)
        xs[idx >> 8][idx & 255] = X[(size_t)b0 * Hv + idx];
    __syncthreads();

    int n = blockIdx.x * 8 + w;
    const float* wr = W + (size_t)n * 256 + lane * 4;
    float4 w0 = *(const float4*)(wr);
    float4 w1 = *(const float4*)(wr + 128);
    float bvl = bias[n];

#pragma unroll 4
    for (int bb = 0; bb < 32; bb++) {
        const float* xr = &xs[bb][lane * 4];
        float4 x0 = *(const float4*)(xr);
        float4 x1 = *(const float4*)(xr + 128);
        float p = w0.x * x0.x + w0.y * x0.y + w0.z * x0.z + w0.w * x0.w
                + w1.x * x1.x + w1.y * x1.y + w1.z * x1.z + w1.w * x1.w;
#pragma unroll
        for (int o = 16; o; o >>= 1) p += __shfl_xor_sync(0xffffffffu, p, o);
        if (lane == 0) Y[(b0 + bb) * 768 + n] = p + bvl;
    }
}

// ---------------- K2c: GRU elementwise + h transpose ----------------
__global__ void k_gru(const float* __restrict__ hidden, float* __restrict__ out) {
    int b = blockIdx.x, h = threadIdx.x;
    float xr = g_gx[b * 768 + h],        hr = g_gh[b * 768 + h];
    float xz = g_gx[b * 768 + 256 + h],  hz = g_gh[b * 768 + 256 + h];
    float xn = g_gx[b * 768 + 512 + h],  hn = g_gh[b * 768 + 512 + h];
    float r = sigmoid_fast(xr + hr);
    float z = sigmoid_fast(xz + hz);
    float n = tanh_fast(xn + r * hn);
    float hprev = hidden[b * Hv + h];
    float hnew = (1.f - z) * n + z * hprev;
    out[HNEW_OFF + b * Hv + h] = hnew;
    g_ht[h * Bv + b] = hnew;
}

// ---------------- K3: logits GEMM via tf32 mma.sync ----------------
#define SW_STR 36
#define SH_STR 132
#define RES_STR 132
#define SW_SZ  (128 * SW_STR)
#define SH_SZ  (32 * SH_STR)
__global__ void __launch_bounds__(256, 2) k_logits(const float* __restrict__ Wv,
                                                   const float* __restrict__ out_b,
                                                   float* __restrict__ out) {
    __shared__ __align__(16) uint32_t smem[SW_SZ + SH_SZ];
    __shared__ __align__(16) float s_bias[128];
    uint32_t* s_w = smem;
    uint32_t* s_h = smem + SW_SZ;
    float* res = (float*)smem;

    int tid = threadIdx.x, wid = tid >> 5, lane = tid & 31;
    int wm = wid & 3, wn = wid >> 2;
    int vb = blockIdx.x * 128;
    int lr = lane >> 2;
    int lc = lane & 3;

    if (tid < 128) s_bias[tid] = out_b[vb + tid];

    float acc[2][8][4];
#pragma unroll
    for (int mt = 0; mt < 2; mt++)
#pragma unroll
        for (int j = 0; j < 8; j++)
#pragma unroll
            for (int c = 0; c < 4; c++) acc[mt][j][c] = 0.f;

    for (int kc = 0; kc < 256; kc += 32) {
        __syncthreads();
        {
            int k4 = (tid & 7) * 4;
#pragma unroll
            for (int i = 0; i < 4; i++) {
                int v = (tid >> 3) + i * 32;
                float4 wv = *(const float4*)(Wv + (size_t)(vb + v) * 256 + kc + k4);
                uint32_t* d = s_w + v * SW_STR + k4;
                d[0] = to_tf32(wv.x); d[1] = to_tf32(wv.y);
                d[2] = to_tf32(wv.z); d[3] = to_tf32(wv.w);
            }
        }
        {
            int n4 = (tid & 31) * 4;
#pragma unroll
            for (int i = 0; i < 4; i++) {
                int k = (tid >> 5) + i * 8;
                float4 hv = *(const float4*)(g_ht + (size_t)(kc + k) * 128 + n4);
                uint32_t* d = s_h + k * SH_STR + n4;
                d[0] = to_tf32(hv.x); d[1] = to_tf32(hv.y);
                d[2] = to_tf32(hv.z); d[3] = to_tf32(hv.w);
            }
        }
        __syncthreads();

#pragma unroll
        for (int ks = 0; ks < 4; ks++) {
            int kk = ks * 8;
            uint32_t af[2][4];
#pragma unroll
            for (int mt = 0; mt < 2; mt++) {
                int row = wm * 32 + mt * 16 + lr;
                af[mt][0] = s_w[row * SW_STR + kk + lc];
                af[mt][1] = s_w[(row + 8) * SW_STR + kk + lc];
                af[mt][2] = s_w[row * SW_STR + kk + 4 + lc];
                af[mt][3] = s_w[(row + 8) * SW_STR + kk + 4 + lc];
            }
            uint32_t bf[8][2];
#pragma unroll
            for (int j = 0; j < 8; j++) {
                int n = wn * 64 + j * 8 + lr;
                bf[j][0] = s_h[(kk + lc) * SH_STR + n];
                bf[j][1] = s_h[(kk + 4 + lc) * SH_STR + n];
            }
#pragma unroll
            for (int mt = 0; mt < 2; mt++)
#pragma unroll
                for (int j = 0; j < 8; j++)
                    mma_tf32(acc[mt][j], af[mt][0], af[mt][1], af[mt][2], af[mt][3],
                             bf[j][0], bf[j][1]);
        }
    }

    for (int h = 0; h < 2; h++) {
        __syncthreads();
        if (wn == h) {
#pragma unroll
            for (int mt = 0; mt < 2; mt++)
#pragma unroll
                for (int j = 0; j < 8; j++) {
                    int v0 = wm * 32 + mt * 16 + lr;
                    int b0 = j * 8 + lc * 2;
                    res[(b0    ) * RES_STR + v0    ] = acc[mt][j][0] + s_bias[v0];
                    res[(b0 + 1) * RES_STR + v0    ] = acc[mt][j][1] + s_bias[v0];
                    res[(b0    ) * RES_STR + v0 + 8] = acc[mt][j][2] + s_bias[v0 + 8];
                    res[(b0 + 1) * RES_STR + v0 + 8] = acc[mt][j][3] + s_bias[v0 + 8];
                }
        }
        __syncthreads();
#pragma unroll
        for (int i = 0; i < 32; i++) {
            int idx = i * 256 + tid;
            int bb = idx >> 7, v = idx & 127;
            out[(size_t)(h * 64 + bb) * Vv + vb + v] = res[bb * RES_STR + v];
        }
#pragma unroll
        for (int rr = 0; rr < 8; rr++) {
            int r = wid * 8 + rr;
            float4 x = *(const float4*)&res[r * RES_STR + lane * 4];
            float mx = fmaxf(fmaxf(x.x, x.y), fmaxf(x.z, x.w));
#pragma unroll
            for (int o = 16; o; o >>= 1) mx = fmaxf(mx, __shfl_xor_sync(0xffffffffu, mx, o));
            float se = __expf(x.x - mx) + __expf(x.y - mx) + __expf(x.z - mx) + __expf(x.w - mx);
#pragma unroll
            for (int o = 16; o; o >>= 1) se += __shfl_xor_sync(0xffffffffu, se, o);
            if (lane == 0) {
                int gb = h * 64 + r;
                g_pmax[blockIdx.x * Bv + gb] = mx;
                g_psum[blockIdx.x * Bv + gb] = se;
            }
        }
    }
}

// ---------------- K4: log_softmax finalize (v-split) ----------------
__global__ void __launch_bounds__(512) k_lsm(float* __restrict__ out) {
    int b = blockIdx.x, y = blockIdx.y;
    int tid = threadIdx.x, w = tid >> 5, lane = tid & 31;
    float m = NEG_HUGE, l = 0.f;
    for (int i = tid; i < NTILES; i += 512) {
        float mx = g_pmax[i * Bv + b];
        float se = g_psum[i * Bv + b];
        float nm = fmaxf(m, mx);
        l = l * __expf(m - nm) + se * __expf(mx - nm);
        m = nm;
    }
#pragma unroll
    for (int o = 16; o; o >>= 1) {
        float m2 = __shfl_xor_sync(0xffffffffu, m, o);
        float l2 = __shfl_xor_sync(0xffffffffu, l, o);
        float nm = fmaxf(m, m2);
        l = l * __expf(m - nm) + l2 * __expf(m2 - nm);
        m = nm;
    }
    __shared__ float sm[16], sl[16];
    if (lane == 0) { sm[w] = m; sl[w] = l; }
    __syncthreads();
    float M = NEG_HUGE;
#pragma unroll
    for (int i = 0; i < 16; i++) M = fmaxf(M, sm[i]);
    float L = 0.f;
#pragma unroll
    for (int i = 0; i < 16; i++) L += sl[i] * __expf(sm[i] - M);
    float lse = M + logf(L);

    float* row = out + (size_t)b * Vv;
    int vend = (y + 1) * 8000;
    for (int v = y * 8000 + tid; v < vend; v += 512) row[v] -= lse;
}

// ---------------- launch ----------------
extern "C" void kernel_launch(void* const* d_in, const int* in_sizes, int n_in,
                              void* d_out, int out_size) {
    const int*   tokens    = (const int*)d_in[0];
    const float* hidden    = (const float*)d_in[1];
    const float* enc       = (const float*)d_in[2];
    const float* emb_table = (const float*)d_in[3];
    const float* attn_W    = (const float*)d_in[4];
    const float* attn_b    = (const float*)d_in[5];
    const float* comb_W    = (const float*)d_in[6];
    const float* comb_b    = (const float*)d_in[7];
    const float* gru_Wih   = (const float*)d_in[8];
    const float* gru_Whh   = (const float*)d_in[9];
    const float* gru_bih   = (const float*)d_in[10];
    const float* gru_bhh   = (const float*)d_in[11];
    const float* out_W     = (const float*)d_in[12];
    const float* out_b     = (const float*)d_in[13];
    float* out = (float*)d_out;

    k_attn_part<<<dim3(NCH, Bv), 512>>>(enc, attn_W, hidden, attn_b, out);
    k_attn_fin<<<Bv, 512>>>(out);
    k_comb<<<dim3(32, 8), 256>>>(tokens, emb_table, comb_W, comb_b, out);
    k_gxgh<<<dim3(96, 4, 2), 256>>>(hidden, gru_Wih, gru_Whh, gru_bih, gru_bhh);
    k_gru<<<Bv, 256>>>(hidden, out);
    k_logits<<<NTILES, 256>>>(out_W, out_b, out);
    k_lsm<<<dim3(Bv, 4), 512>>>(out);
}